// round 13
// baseline (speedup 1.0000x reference)
#include <cuda_runtime.h>

// ----------------------------------------------------------------------------
// LSTM autoencoder, fp32: pre-transposed weights (R12) + 8x8 FFMA2 tile (R10).
// B=65536, T=8, D=60, H=128, L=64. PyTorch gate order i,f,g,o.
//
// R12 finding: in-loop weight transpose was the dominant crossbar consumer ->
// prologue kernel transposes all 8 weight matrices to WT[k][512] once; layer
// kernels stage chunks with a flat coalesced LDG.128 -> STS.128 copy.
// This round: 8-row x 8-col thread tile (warp = row-group x column-half),
// halving weight LDS bytes/FMA (1.0 -> 0.5) at 128 regs / 2 CTAs/SM.
//
// Per CTA: M=32 rows, 256 threads (8 warps). Warp ty: rg=ty>>1 (rows 8*rg..+7),
// ch=ty&1. Thread owns gate cols {64*ch + 2*tx + e + 128*j : e=0..1, j=0..3}
// -> 32 u64 accumulators via fma.rn.f32x2. Weights: conflict-free LDS.64
// (lane stride 8B); acts: warp-broadcast float2. c-state in regs; h in smem.
// MODE 0: h sequence out; MODE 1: z = h_last@W_lat^T+b; MODE 2: per-t
// out_t = h_t@W_out^T+b (conflict-free pitch-132 float4 epilogue).
// ----------------------------------------------------------------------------

typedef unsigned long long u64;

#define CB 65536
#define CT 8
#define CD 60
#define CH 128
#define CL 64
#define MR 32
#define NT 256

__device__ float g_h1[(size_t)CB * CT * CH]; // 256 MB
__device__ float g_d1[(size_t)CB * CT * CH]; // 256 MB
__device__ float g_z [(size_t)CB * CL];      // 16 MB
// transposed weights: 8 matrices, total (60+128+64+128 + 4*128) = 892 rows x 512
__device__ float g_wt[892 * 512];

__device__ __forceinline__ float sigf(float x)     { return 1.f / (1.f + __expf(-x)); }
__device__ __forceinline__ float tanhfast(float x) { return 2.f / (1.f + __expf(-2.f * x)) - 1.f; }

__device__ __forceinline__ void ffma2(u64& d, u64 a, u64 b) {
    asm("fma.rn.f32x2 %0, %1, %2, %0;" : "+l"(d) : "l"(a), "l"(b));
}
__device__ __forceinline__ u64 pack2(float x) {
    u64 v; asm("mov.b64 %0, {%1, %1};" : "=l"(v) : "f"(x)); return v;
}
__device__ __forceinline__ float2 unpack2(u64 v) {
    float2 f; asm("mov.b64 {%0, %1}, %2;" : "=f"(f.x), "=f"(f.y) : "l"(v)); return f;
}

// ---- prologue: WT[k*512 + c] = W[c*KD + k] (coalesced writes) ----
__global__ void transpose_w(const float* __restrict__ W, float* __restrict__ WT, int KD)
{
    int i = blockIdx.x * blockDim.x + threadIdx.x;
    if (i < KD * 512) {
        int k = i >> 9, c = i & 511;
        WT[i] = W[c * KD + k];
    }
}

// stage one 16-k chunk of WT [KD x 512] (k-major) into smem: flat coalesced copy.
template <int KD>
__device__ __forceinline__ void stage_chunkT(const float* __restrict__ WT, int ci,
                                             float* __restrict__ Wt, int tid)
{
    const int k0   = 16 * ci;
    const int klen = (KD - k0 < 16) ? (KD - k0) : 16;
    const float4* src = (const float4*)(WT + (size_t)k0 * 512);
    float4* dst = (float4*)Wt;
    const int n4 = klen * 128;
#pragma unroll
    for (int l = 0; l < 8; ++l) {
        int i = tid + l * NT;
        if (i < n4) dst[i] = src[i];
    }
}

// compute one staged chunk: act rows r0..r0+7 (this thread), nk2 groups of 2 k.
// cb0 = 64*ch + 2*tx : this thread's column pair base within each gate.
__device__ __forceinline__ void gemm_chunk2(const float* __restrict__ act, int pitch,
                                            const float* __restrict__ Wt, int cb0,
                                            u64 (&acc)[8][4], int nk2)
{
    for (int q = 0; q < nk2; ++q) {
        float2 a[8];
#pragma unroll
        for (int r = 0; r < 8; ++r)
            a[r] = *(const float2*)(act + r * pitch + 2 * q);
#pragma unroll
        for (int kk = 0; kk < 2; ++kk) {
            const float* wb = Wt + (2 * q + kk) * 512 + cb0;
            u64 w0 = *(const u64*)(wb);
            u64 w1 = *(const u64*)(wb + 128);
            u64 w2 = *(const u64*)(wb + 256);
            u64 w3 = *(const u64*)(wb + 384);
#pragma unroll
            for (int r = 0; r < 8; ++r) {
                u64 p = pack2(kk ? a[r].y : a[r].x);
                ffma2(acc[r][0], p, w0);
                ffma2(acc[r][1], p, w1);
                ffma2(acc[r][2], p, w2);
                ffma2(acc[r][3], p, w3);
            }
        }
    }
}

// one full GEMM pass over transposed weights WT [KD x 512] against act.
template <int KD>
__device__ __forceinline__ void gemm_pass(const float* __restrict__ WT,
                                          const float* __restrict__ act, int pitch,
                                          float* __restrict__ Wt0, float* __restrict__ Wt1,
                                          int tid, int cb0, u64 (&acc)[8][4])
{
    constexpr int NCH = (KD + 15) >> 4;
    stage_chunkT<KD>(WT, 0, Wt0, tid);
    __syncthreads();
#pragma unroll
    for (int ci = 0; ci < NCH; ++ci) {
        float* cw = (ci & 1) ? Wt1 : Wt0;
        float* nw = (ci & 1) ? Wt0 : Wt1;
        if (ci + 1 < NCH) stage_chunkT<KD>(WT, ci + 1, nw, tid);
        const int klen = (KD - 16 * ci < 16) ? (KD - 16 * ci) : 16;
        gemm_chunk2(act + 16 * ci, pitch, cw, cb0, acc, klen >> 1);
        __syncthreads();
    }
}

template <int DIN, int MODE, int BCAST>
__global__ __launch_bounds__(NT, 2)
void lstm_kernel(const float* __restrict__ X,
                 const float* __restrict__ WihT, const float* __restrict__ WhhT,
                 const float* __restrict__ bih, const float* __restrict__ bhh,
                 const float* __restrict__ Waux, const float* __restrict__ baux,
                 float* __restrict__ OutSeq, float* __restrict__ OutAux)
{
    constexpr int XP = (DIN + 3) & ~3;       // padded act pitch (60/64/128)
    extern __shared__ float sm[];
    float* Hbuf   = sm;                       // 4096
    float* Xbuf   = sm + 4096;                // 32*XP
    float* bias_s = Xbuf + MR * XP;           // 512
    float* Wt0    = bias_s + 512;             // 8192
    float* Wt1    = Wt0 + 8192;               // 8192
    float* Waux_s = Wt0 + 16384;              // MODE2: 60*132 = 7920

    const int tid = threadIdx.x;
    const int tx  = tid & 31;
    const int ty  = tid >> 5;                 // 0..7
    const int r0  = (ty >> 1) * 8;            // row group base
    const int cb0 = (ty & 1) * 64 + 2 * tx;   // column pair base within a gate
    const int rowbase = blockIdx.x * MR;

    for (int i = tid; i < 512; i += NT) bias_s[i] = bih[i] + bhh[i];
    if (MODE == 2) {
        for (int i = tid; i < CD * CH; i += NT) {
            int c = i >> 7, k = i & 127;
            Waux_s[c * 132 + k] = Waux[i];
        }
    }
    if (BCAST) {
        constexpr int VPR = DIN / 4;
        for (int i = tid; i < MR * VPR; i += NT) {
            int r = i / VPR, v = i - r * VPR;
            *(float4*)(Xbuf + r * XP + 4 * v) =
                *((const float4*)(X + (size_t)(rowbase + r) * DIN) + v);
        }
    }

    float cst[8][2];
#pragma unroll
    for (int r = 0; r < 8; r++) { cst[r][0] = 0.f; cst[r][1] = 0.f; }
    u64 acc[8][4];
    __syncthreads(); // bias/Waux/Xbuf(bcast) visible

    for (int t = 0; t < CT; ++t) {
        if (!BCAST) {
            constexpr int VPR = DIN / 4; // 15 or 32
            for (int i = tid; i < MR * VPR; i += NT) {
                int r = i / VPR, v = i - r * VPR;
                *(float4*)(Xbuf + r * XP + 4 * v) =
                    *((const float4*)(X + ((size_t)(rowbase + r) * CT + t) * DIN) + v);
            }
        }
        // acc init from bias (one u64 per gate, replicated to 8 rows)
        {
            const float* bb = bias_s + cb0;
#pragma unroll
            for (int j = 0; j < 4; j++) {
                u64 b = *(const u64*)(bb + 128 * j);
#pragma unroll
                for (int r = 0; r < 8; r++) acc[r][j] = b;
            }
        }

        gemm_pass<DIN>(WihT, Xbuf + r0 * XP, XP, Wt0, Wt1, tid, cb0, acc);
        if (t > 0)
            gemm_pass<CH>(WhhT, Hbuf + r0 * CH, CH, Wt0, Wt1, tid, cb0, acc);
        __syncthreads(); // all reads of Hbuf/Xbuf for this timestep complete

        // ---- cell update; thread h-cols = cb0 + {0,1} ----
#pragma unroll
        for (int r = 0; r < 8; r++) {
            float2 iv = unpack2(acc[r][0]);
            float2 fv = unpack2(acc[r][1]);
            float2 gv = unpack2(acc[r][2]);
            float2 ov = unpack2(acc[r][3]);
            float h0, h1;
            {
                float ig = sigf(iv.x), fg = sigf(fv.x);
                float gg = tanhfast(gv.x), og = sigf(ov.x);
                float cv = fmaf(fg, cst[r][0], ig * gg);
                cst[r][0] = cv;
                h0 = og * tanhfast(cv);
            }
            {
                float ig = sigf(iv.y), fg = sigf(fv.y);
                float gg = tanhfast(gv.y), og = sigf(ov.y);
                float cv = fmaf(fg, cst[r][1], ig * gg);
                cst[r][1] = cv;
                h1 = og * tanhfast(cv);
            }
            float2 h2 = make_float2(h0, h1);
            *(float2*)(Hbuf + (r0 + r) * CH + cb0) = h2;
            if (MODE == 0) {
                *(float2*)(OutSeq + ((size_t)(rowbase + r0 + r) * CT + t) * CH + cb0) = h2;
            }
        }

        if (MODE == 2) {
            __syncthreads(); // h_t complete in Hbuf
            // out_t[32][60] = h_t @ W_out^T + b_out ; r warp-uniform -> broadcast h,
            // Waux pitch 132 -> conflict-free float4 per 8-lane phase.
#pragma unroll
            for (int l = 0; l < 8; l++) {
                int i = tid + l * NT;
                int r = i >> 6, c = i & 63;
                if (c < CD) {
                    const float4* h4 = (const float4*)(Hbuf + r * CH);
                    const float4* w4 = (const float4*)(Waux_s + c * 132);
                    float sum = __ldg(baux + c);
#pragma unroll 8
                    for (int k4 = 0; k4 < 32; k4++) {
                        float4 hh = h4[k4], ww = w4[k4];
                        sum = fmaf(hh.x, ww.x, sum); sum = fmaf(hh.y, ww.y, sum);
                        sum = fmaf(hh.z, ww.z, sum); sum = fmaf(hh.w, ww.w, sum);
                    }
                    OutAux[((size_t)(rowbase + r) * CT + t) * CD + c] = sum;
                }
            }
            // next t's first pass barrier orders any Wt/Hbuf re-writes after this.
        }
    }

    if (MODE == 1) {
        // z[32][64] = h_last @ W_lat^T + b_lat ; stage W_lat at pitch 132 in Wt region
        __syncthreads();
        for (int i = tid; i < CL * CH; i += NT) {
            int c = i >> 7, k = i & 127;
            Wt0[c * 132 + k] = Waux[i]; // 16384-float Wt region fits 64*132
        }
        __syncthreads();
#pragma unroll
        for (int l = 0; l < 8; l++) {
            int i = tid + l * NT;
            int r = i >> 6, c = i & 63;
            const float4* h4 = (const float4*)(Hbuf + r * CH);
            const float4* w4 = (const float4*)(Wt0 + c * 132);
            float sum = __ldg(baux + c);
#pragma unroll 8
            for (int k4 = 0; k4 < 32; k4++) {
                float4 hh = h4[k4], ww = w4[k4];
                sum = fmaf(hh.x, ww.x, sum); sum = fmaf(hh.y, ww.y, sum);
                sum = fmaf(hh.z, ww.z, sum); sum = fmaf(hh.w, ww.w, sum);
            }
            OutAux[(size_t)(rowbase + r) * CL + c] = sum;
        }
    }
}

// ----------------------------------------------------------------------------

extern "C" void kernel_launch(void* const* d_in, const int* in_sizes, int n_in,
                              void* d_out, int out_size)
{
    const float* x     = (const float*)d_in[0];
    const float* e0Wih = (const float*)d_in[1];
    const float* e0Whh = (const float*)d_in[2];
    const float* e0bih = (const float*)d_in[3];
    const float* e0bhh = (const float*)d_in[4];
    const float* e1Wih = (const float*)d_in[5];
    const float* e1Whh = (const float*)d_in[6];
    const float* e1bih = (const float*)d_in[7];
    const float* e1bhh = (const float*)d_in[8];
    const float* d0Wih = (const float*)d_in[9];
    const float* d0Whh = (const float*)d_in[10];
    const float* d0bih = (const float*)d_in[11];
    const float* d0bhh = (const float*)d_in[12];
    const float* d1Wih = (const float*)d_in[13];
    const float* d1Whh = (const float*)d_in[14];
    const float* d1bih = (const float*)d_in[15];
    const float* d1bhh = (const float*)d_in[16];
    const float* Wlat  = (const float*)d_in[17];
    const float* blat  = (const float*)d_in[18];
    const float* Wout  = (const float*)d_in[19];
    const float* bout  = (const float*)d_in[20];
    float* out = (float*)d_out;

    float *h1p, *d1p, *zp, *wtp;
    cudaGetSymbolAddress((void**)&h1p, g_h1);
    cudaGetSymbolAddress((void**)&d1p, g_d1);
    cudaGetSymbolAddress((void**)&zp,  g_z);
    cudaGetSymbolAddress((void**)&wtp, g_wt);

    // WT region offsets (rows of 512)
    const int R_E0IH = 0;            // KD=60
    const int R_E0HH = 60;           // KD=128
    const int R_E1IH = 188;          // KD=128
    const int R_E1HH = 316;          // KD=128
    const int R_D0IH = 444;          // KD=64
    const int R_D0HH = 508;          // KD=128
    const int R_D1IH = 636;          // KD=128
    const int R_D1HH = 764;          // KD=128  (end 892)

    struct { const float* src; int off; int kd; } tw[8] = {
        { e0Wih, R_E0IH, 60  }, { e0Whh, R_E0HH, 128 },
        { e1Wih, R_E1IH, 128 }, { e1Whh, R_E1HH, 128 },
        { d0Wih, R_D0IH, 64  }, { d0Whh, R_D0HH, 128 },
        { d1Wih, R_D1IH, 128 }, { d1Whh, R_D1HH, 128 },
    };
    for (int m = 0; m < 8; ++m) {
        int n = tw[m].kd * 512;
        transpose_w<<<(n + 255) / 256, 256>>>(tw[m].src, wtp + (size_t)tw[m].off * 512,
                                              tw[m].kd);
    }

    // smem (floats): Hbuf 4096 + Xbuf 32*XP + bias 512 + Wt 16384 (+ MODE2 7920)
    const int SM_ENC0 = (4096 + 32 * 60  + 512 + 16384) * 4;          // 91,648
    const int SM_ENC1 = (4096 + 32 * 128 + 512 + 16384) * 4;          // 100,352
    const int SM_DEC0 = (4096 + 32 * 64  + 512 + 16384) * 4;          // 92,160
    const int SM_DEC1 = (4096 + 32 * 128 + 512 + 16384 + 7920) * 4;   // 132,032

    cudaFuncSetAttribute((const void*)lstm_kernel<60, 0, 0>,
                         cudaFuncAttributeMaxDynamicSharedMemorySize, SM_ENC0);
    cudaFuncSetAttribute((const void*)lstm_kernel<128, 1, 0>,
                         cudaFuncAttributeMaxDynamicSharedMemorySize, SM_ENC1);
    cudaFuncSetAttribute((const void*)lstm_kernel<64, 0, 1>,
                         cudaFuncAttributeMaxDynamicSharedMemorySize, SM_DEC0);
    cudaFuncSetAttribute((const void*)lstm_kernel<128, 2, 0>,
                         cudaFuncAttributeMaxDynamicSharedMemorySize, SM_DEC1);

    dim3 grid(CB / MR); // 2048 CTAs

    // encoder layer 0: x [B,T,60] -> h1 seq [B,T,128]
    lstm_kernel<60, 0, 0><<<grid, NT, SM_ENC0>>>(
        x, wtp + (size_t)R_E0IH * 512, wtp + (size_t)R_E0HH * 512,
        e0bih, e0bhh, nullptr, nullptr, h1p, nullptr);
    // encoder layer 1: h1 -> h_last -> z [B,64]
    lstm_kernel<128, 1, 0><<<grid, NT, SM_ENC1>>>(
        h1p, wtp + (size_t)R_E1IH * 512, wtp + (size_t)R_E1HH * 512,
        e1bih, e1bhh, Wlat, blat, nullptr, zp);
    // decoder layer 0: z broadcast over T -> d1 seq [B,T,128]
    lstm_kernel<64, 0, 1><<<grid, NT, SM_DEC0>>>(
        zp, wtp + (size_t)R_D0IH * 512, wtp + (size_t)R_D0HH * 512,
        d0bih, d0bhh, nullptr, nullptr, d1p, nullptr);
    // decoder layer 1 + output projection: d1 -> recon [B,T,60]
    lstm_kernel<128, 2, 0><<<grid, NT, SM_DEC1>>>(
        d1p, wtp + (size_t)R_D1IH * 512, wtp + (size_t)R_D1HH * 512,
        d1bih, d1bhh, Wout, bout, nullptr, out);
}

// round 14
// speedup vs baseline: 1.0006x; 1.0006x over previous
#include <cuda_runtime.h>

// ----------------------------------------------------------------------------
// LSTM autoencoder, fp32: pre-transposed weights (R12) + 8x8 FFMA2 tile (R10).
// B=65536, T=8, D=60, H=128, L=64. PyTorch gate order i,f,g,o.
//
// R12 finding: in-loop weight transpose was the dominant crossbar consumer ->
// prologue kernel transposes all 8 weight matrices to WT[k][512] once; layer
// kernels stage chunks with a flat coalesced LDG.128 -> STS.128 copy.
// This round: 8-row x 8-col thread tile (warp = row-group x column-half),
// halving weight LDS bytes/FMA (1.0 -> 0.5) at 128 regs / 2 CTAs/SM.
//
// Per CTA: M=32 rows, 256 threads (8 warps). Warp ty: rg=ty>>1 (rows 8*rg..+7),
// ch=ty&1. Thread owns gate cols {64*ch + 2*tx + e + 128*j : e=0..1, j=0..3}
// -> 32 u64 accumulators via fma.rn.f32x2. Weights: conflict-free LDS.64
// (lane stride 8B); acts: warp-broadcast float2. c-state in regs; h in smem.
// MODE 0: h sequence out; MODE 1: z = h_last@W_lat^T+b; MODE 2: per-t
// out_t = h_t@W_out^T+b (conflict-free pitch-132 float4 epilogue).
// ----------------------------------------------------------------------------

typedef unsigned long long u64;

#define CB 65536
#define CT 8
#define CD 60
#define CH 128
#define CL 64
#define MR 32
#define NT 256

__device__ float g_h1[(size_t)CB * CT * CH]; // 256 MB
__device__ float g_d1[(size_t)CB * CT * CH]; // 256 MB
__device__ float g_z [(size_t)CB * CL];      // 16 MB
// transposed weights: 8 matrices, total (60+128+64+128 + 4*128) = 892 rows x 512
__device__ float g_wt[892 * 512];

__device__ __forceinline__ float sigf(float x)     { return 1.f / (1.f + __expf(-x)); }
__device__ __forceinline__ float tanhfast(float x) { return 2.f / (1.f + __expf(-2.f * x)) - 1.f; }

__device__ __forceinline__ void ffma2(u64& d, u64 a, u64 b) {
    asm("fma.rn.f32x2 %0, %1, %2, %0;" : "+l"(d) : "l"(a), "l"(b));
}
__device__ __forceinline__ u64 pack2(float x) {
    u64 v; asm("mov.b64 %0, {%1, %1};" : "=l"(v) : "f"(x)); return v;
}
__device__ __forceinline__ float2 unpack2(u64 v) {
    float2 f; asm("mov.b64 {%0, %1}, %2;" : "=f"(f.x), "=f"(f.y) : "l"(v)); return f;
}

// ---- prologue: WT[k*512 + c] = W[c*KD + k] (coalesced writes) ----
__global__ void transpose_w(const float* __restrict__ W, float* __restrict__ WT, int KD)
{
    int i = blockIdx.x * blockDim.x + threadIdx.x;
    if (i < KD * 512) {
        int k = i >> 9, c = i & 511;
        WT[i] = W[c * KD + k];
    }
}

// stage one 16-k chunk of WT [KD x 512] (k-major) into smem: flat coalesced copy.
template <int KD>
__device__ __forceinline__ void stage_chunkT(const float* __restrict__ WT, int ci,
                                             float* __restrict__ Wt, int tid)
{
    const int k0   = 16 * ci;
    const int klen = (KD - k0 < 16) ? (KD - k0) : 16;
    const float4* src = (const float4*)(WT + (size_t)k0 * 512);
    float4* dst = (float4*)Wt;
    const int n4 = klen * 128;
#pragma unroll
    for (int l = 0; l < 8; ++l) {
        int i = tid + l * NT;
        if (i < n4) dst[i] = src[i];
    }
}

// compute one staged chunk: act rows r0..r0+7 (this thread), nk2 groups of 2 k.
// cb0 = 64*ch + 2*tx : this thread's column pair base within each gate.
__device__ __forceinline__ void gemm_chunk2(const float* __restrict__ act, int pitch,
                                            const float* __restrict__ Wt, int cb0,
                                            u64 (&acc)[8][4], int nk2)
{
    for (int q = 0; q < nk2; ++q) {
        float2 a[8];
#pragma unroll
        for (int r = 0; r < 8; ++r)
            a[r] = *(const float2*)(act + r * pitch + 2 * q);
#pragma unroll
        for (int kk = 0; kk < 2; ++kk) {
            const float* wb = Wt + (2 * q + kk) * 512 + cb0;
            u64 w0 = *(const u64*)(wb);
            u64 w1 = *(const u64*)(wb + 128);
            u64 w2 = *(const u64*)(wb + 256);
            u64 w3 = *(const u64*)(wb + 384);
#pragma unroll
            for (int r = 0; r < 8; ++r) {
                u64 p = pack2(kk ? a[r].y : a[r].x);
                ffma2(acc[r][0], p, w0);
                ffma2(acc[r][1], p, w1);
                ffma2(acc[r][2], p, w2);
                ffma2(acc[r][3], p, w3);
            }
        }
    }
}

// one full GEMM pass over transposed weights WT [KD x 512] against act.
template <int KD>
__device__ __forceinline__ void gemm_pass(const float* __restrict__ WT,
                                          const float* __restrict__ act, int pitch,
                                          float* __restrict__ Wt0, float* __restrict__ Wt1,
                                          int tid, int cb0, u64 (&acc)[8][4])
{
    constexpr int NCH = (KD + 15) >> 4;
    stage_chunkT<KD>(WT, 0, Wt0, tid);
    __syncthreads();
#pragma unroll
    for (int ci = 0; ci < NCH; ++ci) {
        float* cw = (ci & 1) ? Wt1 : Wt0;
        float* nw = (ci & 1) ? Wt0 : Wt1;
        if (ci + 1 < NCH) stage_chunkT<KD>(WT, ci + 1, nw, tid);
        const int klen = (KD - 16 * ci < 16) ? (KD - 16 * ci) : 16;
        gemm_chunk2(act + 16 * ci, pitch, cw, cb0, acc, klen >> 1);
        __syncthreads();
    }
}

template <int DIN, int MODE, int BCAST>
__global__ __launch_bounds__(NT, 2)
void lstm_kernel(const float* __restrict__ X,
                 const float* __restrict__ WihT, const float* __restrict__ WhhT,
                 const float* __restrict__ bih, const float* __restrict__ bhh,
                 const float* __restrict__ Waux, const float* __restrict__ baux,
                 float* __restrict__ OutSeq, float* __restrict__ OutAux)
{
    constexpr int XP = (DIN + 3) & ~3;       // padded act pitch (60/64/128)
    extern __shared__ float sm[];
    float* Hbuf   = sm;                       // 4096
    float* Xbuf   = sm + 4096;                // 32*XP
    float* bias_s = Xbuf + MR * XP;           // 512
    float* Wt0    = bias_s + 512;             // 8192
    float* Wt1    = Wt0 + 8192;               // 8192
    float* Waux_s = Wt0 + 16384;              // MODE2: 60*132 = 7920

    const int tid = threadIdx.x;
    const int tx  = tid & 31;
    const int ty  = tid >> 5;                 // 0..7
    const int r0  = (ty >> 1) * 8;            // row group base
    const int cb0 = (ty & 1) * 64 + 2 * tx;   // column pair base within a gate
    const int rowbase = blockIdx.x * MR;

    for (int i = tid; i < 512; i += NT) bias_s[i] = bih[i] + bhh[i];
    if (MODE == 2) {
        for (int i = tid; i < CD * CH; i += NT) {
            int c = i >> 7, k = i & 127;
            Waux_s[c * 132 + k] = Waux[i];
        }
    }
    if (BCAST) {
        constexpr int VPR = DIN / 4;
        for (int i = tid; i < MR * VPR; i += NT) {
            int r = i / VPR, v = i - r * VPR;
            *(float4*)(Xbuf + r * XP + 4 * v) =
                *((const float4*)(X + (size_t)(rowbase + r) * DIN) + v);
        }
    }

    float cst[8][2];
#pragma unroll
    for (int r = 0; r < 8; r++) { cst[r][0] = 0.f; cst[r][1] = 0.f; }
    u64 acc[8][4];
    __syncthreads(); // bias/Waux/Xbuf(bcast) visible

    for (int t = 0; t < CT; ++t) {
        if (!BCAST) {
            constexpr int VPR = DIN / 4; // 15 or 32
            for (int i = tid; i < MR * VPR; i += NT) {
                int r = i / VPR, v = i - r * VPR;
                *(float4*)(Xbuf + r * XP + 4 * v) =
                    *((const float4*)(X + ((size_t)(rowbase + r) * CT + t) * DIN) + v);
            }
        }
        // acc init from bias (one u64 per gate, replicated to 8 rows)
        {
            const float* bb = bias_s + cb0;
#pragma unroll
            for (int j = 0; j < 4; j++) {
                u64 b = *(const u64*)(bb + 128 * j);
#pragma unroll
                for (int r = 0; r < 8; r++) acc[r][j] = b;
            }
        }

        gemm_pass<DIN>(WihT, Xbuf + r0 * XP, XP, Wt0, Wt1, tid, cb0, acc);
        if (t > 0)
            gemm_pass<CH>(WhhT, Hbuf + r0 * CH, CH, Wt0, Wt1, tid, cb0, acc);
        __syncthreads(); // all reads of Hbuf/Xbuf for this timestep complete

        // ---- cell update; thread h-cols = cb0 + {0,1} ----
#pragma unroll
        for (int r = 0; r < 8; r++) {
            float2 iv = unpack2(acc[r][0]);
            float2 fv = unpack2(acc[r][1]);
            float2 gv = unpack2(acc[r][2]);
            float2 ov = unpack2(acc[r][3]);
            float h0, h1;
            {
                float ig = sigf(iv.x), fg = sigf(fv.x);
                float gg = tanhfast(gv.x), og = sigf(ov.x);
                float cv = fmaf(fg, cst[r][0], ig * gg);
                cst[r][0] = cv;
                h0 = og * tanhfast(cv);
            }
            {
                float ig = sigf(iv.y), fg = sigf(fv.y);
                float gg = tanhfast(gv.y), og = sigf(ov.y);
                float cv = fmaf(fg, cst[r][1], ig * gg);
                cst[r][1] = cv;
                h1 = og * tanhfast(cv);
            }
            float2 h2 = make_float2(h0, h1);
            *(float2*)(Hbuf + (r0 + r) * CH + cb0) = h2;
            if (MODE == 0) {
                *(float2*)(OutSeq + ((size_t)(rowbase + r0 + r) * CT + t) * CH + cb0) = h2;
            }
        }

        if (MODE == 2) {
            __syncthreads(); // h_t complete in Hbuf
            // out_t[32][60] = h_t @ W_out^T + b_out ; r warp-uniform -> broadcast h,
            // Waux pitch 132 -> conflict-free float4 per 8-lane phase.
#pragma unroll
            for (int l = 0; l < 8; l++) {
                int i = tid + l * NT;
                int r = i >> 6, c = i & 63;
                if (c < CD) {
                    const float4* h4 = (const float4*)(Hbuf + r * CH);
                    const float4* w4 = (const float4*)(Waux_s + c * 132);
                    float sum = __ldg(baux + c);
#pragma unroll 8
                    for (int k4 = 0; k4 < 32; k4++) {
                        float4 hh = h4[k4], ww = w4[k4];
                        sum = fmaf(hh.x, ww.x, sum); sum = fmaf(hh.y, ww.y, sum);
                        sum = fmaf(hh.z, ww.z, sum); sum = fmaf(hh.w, ww.w, sum);
                    }
                    OutAux[((size_t)(rowbase + r) * CT + t) * CD + c] = sum;
                }
            }
            // next t's first pass barrier orders any Wt/Hbuf re-writes after this.
        }
    }

    if (MODE == 1) {
        // z[32][64] = h_last @ W_lat^T + b_lat ; stage W_lat at pitch 132 in Wt region
        __syncthreads();
        for (int i = tid; i < CL * CH; i += NT) {
            int c = i >> 7, k = i & 127;
            Wt0[c * 132 + k] = Waux[i]; // 16384-float Wt region fits 64*132
        }
        __syncthreads();
#pragma unroll
        for (int l = 0; l < 8; l++) {
            int i = tid + l * NT;
            int r = i >> 6, c = i & 63;
            const float4* h4 = (const float4*)(Hbuf + r * CH);
            const float4* w4 = (const float4*)(Wt0 + c * 132);
            float sum = __ldg(baux + c);
#pragma unroll 8
            for (int k4 = 0; k4 < 32; k4++) {
                float4 hh = h4[k4], ww = w4[k4];
                sum = fmaf(hh.x, ww.x, sum); sum = fmaf(hh.y, ww.y, sum);
                sum = fmaf(hh.z, ww.z, sum); sum = fmaf(hh.w, ww.w, sum);
            }
            OutAux[(size_t)(rowbase + r) * CL + c] = sum;
        }
    }
}

// ----------------------------------------------------------------------------

extern "C" void kernel_launch(void* const* d_in, const int* in_sizes, int n_in,
                              void* d_out, int out_size)
{
    const float* x     = (const float*)d_in[0];
    const float* e0Wih = (const float*)d_in[1];
    const float* e0Whh = (const float*)d_in[2];
    const float* e0bih = (const float*)d_in[3];
    const float* e0bhh = (const float*)d_in[4];
    const float* e1Wih = (const float*)d_in[5];
    const float* e1Whh = (const float*)d_in[6];
    const float* e1bih = (const float*)d_in[7];
    const float* e1bhh = (const float*)d_in[8];
    const float* d0Wih = (const float*)d_in[9];
    const float* d0Whh = (const float*)d_in[10];
    const float* d0bih = (const float*)d_in[11];
    const float* d0bhh = (const float*)d_in[12];
    const float* d1Wih = (const float*)d_in[13];
    const float* d1Whh = (const float*)d_in[14];
    const float* d1bih = (const float*)d_in[15];
    const float* d1bhh = (const float*)d_in[16];
    const float* Wlat  = (const float*)d_in[17];
    const float* blat  = (const float*)d_in[18];
    const float* Wout  = (const float*)d_in[19];
    const float* bout  = (const float*)d_in[20];
    float* out = (float*)d_out;

    float *h1p, *d1p, *zp, *wtp;
    cudaGetSymbolAddress((void**)&h1p, g_h1);
    cudaGetSymbolAddress((void**)&d1p, g_d1);
    cudaGetSymbolAddress((void**)&zp,  g_z);
    cudaGetSymbolAddress((void**)&wtp, g_wt);

    // WT region offsets (rows of 512)
    const int R_E0IH = 0;            // KD=60
    const int R_E0HH = 60;           // KD=128
    const int R_E1IH = 188;          // KD=128
    const int R_E1HH = 316;          // KD=128
    const int R_D0IH = 444;          // KD=64
    const int R_D0HH = 508;          // KD=128
    const int R_D1IH = 636;          // KD=128
    const int R_D1HH = 764;          // KD=128  (end 892)

    struct { const float* src; int off; int kd; } tw[8] = {
        { e0Wih, R_E0IH, 60  }, { e0Whh, R_E0HH, 128 },
        { e1Wih, R_E1IH, 128 }, { e1Whh, R_E1HH, 128 },
        { d0Wih, R_D0IH, 64  }, { d0Whh, R_D0HH, 128 },
        { d1Wih, R_D1IH, 128 }, { d1Whh, R_D1HH, 128 },
    };
    for (int m = 0; m < 8; ++m) {
        int n = tw[m].kd * 512;
        transpose_w<<<(n + 255) / 256, 256>>>(tw[m].src, wtp + (size_t)tw[m].off * 512,
                                              tw[m].kd);
    }

    // smem (floats): Hbuf 4096 + Xbuf 32*XP + bias 512 + Wt 16384 (+ MODE2 7920)
    const int SM_ENC0 = (4096 + 32 * 60  + 512 + 16384) * 4;          // 91,648
    const int SM_ENC1 = (4096 + 32 * 128 + 512 + 16384) * 4;          // 100,352
    const int SM_DEC0 = (4096 + 32 * 64  + 512 + 16384) * 4;          // 92,160
    const int SM_DEC1 = (4096 + 32 * 128 + 512 + 16384 + 7920) * 4;   // 132,032

    cudaFuncSetAttribute((const void*)lstm_kernel<60, 0, 0>,
                         cudaFuncAttributeMaxDynamicSharedMemorySize, SM_ENC0);
    cudaFuncSetAttribute((const void*)lstm_kernel<128, 1, 0>,
                         cudaFuncAttributeMaxDynamicSharedMemorySize, SM_ENC1);
    cudaFuncSetAttribute((const void*)lstm_kernel<64, 0, 1>,
                         cudaFuncAttributeMaxDynamicSharedMemorySize, SM_DEC0);
    cudaFuncSetAttribute((const void*)lstm_kernel<128, 2, 0>,
                         cudaFuncAttributeMaxDynamicSharedMemorySize, SM_DEC1);

    dim3 grid(CB / MR); // 2048 CTAs

    // encoder layer 0: x [B,T,60] -> h1 seq [B,T,128]
    lstm_kernel<60, 0, 0><<<grid, NT, SM_ENC0>>>(
        x, wtp + (size_t)R_E0IH * 512, wtp + (size_t)R_E0HH * 512,
        e0bih, e0bhh, nullptr, nullptr, h1p, nullptr);
    // encoder layer 1: h1 -> h_last -> z [B,64]
    lstm_kernel<128, 1, 0><<<grid, NT, SM_ENC1>>>(
        h1p, wtp + (size_t)R_E1IH * 512, wtp + (size_t)R_E1HH * 512,
        e1bih, e1bhh, Wlat, blat, nullptr, zp);
    // decoder layer 0: z broadcast over T -> d1 seq [B,T,128]
    lstm_kernel<64, 0, 1><<<grid, NT, SM_DEC0>>>(
        zp, wtp + (size_t)R_D0IH * 512, wtp + (size_t)R_D0HH * 512,
        d0bih, d0bhh, nullptr, nullptr, d1p, nullptr);
    // decoder layer 1 + output projection: d1 -> recon [B,T,60]
    lstm_kernel<128, 2, 0><<<grid, NT, SM_DEC1>>>(
        d1p, wtp + (size_t)R_D1IH * 512, wtp + (size_t)R_D1HH * 512,
        d1bih, d1bhh, Wout, bout, nullptr, out);
}

// round 15
// speedup vs baseline: 1.0006x; 1.0000x over previous
#include <cuda_runtime.h>

// ----------------------------------------------------------------------------
// LSTM autoencoder, fp32: pre-transposed weights (R12) + 8x8 FFMA2 tile (R10).
// B=65536, T=8, D=60, H=128, L=64. PyTorch gate order i,f,g,o.
//
// R12 finding: in-loop weight transpose was the dominant crossbar consumer ->
// prologue kernel transposes all 8 weight matrices to WT[k][512] once; layer
// kernels stage chunks with a flat coalesced LDG.128 -> STS.128 copy.
// This round: 8-row x 8-col thread tile (warp = row-group x column-half),
// halving weight LDS bytes/FMA (1.0 -> 0.5) at 128 regs / 2 CTAs/SM.
//
// Per CTA: M=32 rows, 256 threads (8 warps). Warp ty: rg=ty>>1 (rows 8*rg..+7),
// ch=ty&1. Thread owns gate cols {64*ch + 2*tx + e + 128*j : e=0..1, j=0..3}
// -> 32 u64 accumulators via fma.rn.f32x2. Weights: conflict-free LDS.64
// (lane stride 8B); acts: warp-broadcast float2. c-state in regs; h in smem.
// MODE 0: h sequence out; MODE 1: z = h_last@W_lat^T+b; MODE 2: per-t
// out_t = h_t@W_out^T+b (conflict-free pitch-132 float4 epilogue).
// ----------------------------------------------------------------------------

typedef unsigned long long u64;

#define CB 65536
#define CT 8
#define CD 60
#define CH 128
#define CL 64
#define MR 32
#define NT 256

__device__ float g_h1[(size_t)CB * CT * CH]; // 256 MB
__device__ float g_d1[(size_t)CB * CT * CH]; // 256 MB
__device__ float g_z [(size_t)CB * CL];      // 16 MB
// transposed weights: 8 matrices, total (60+128+64+128 + 4*128) = 892 rows x 512
__device__ float g_wt[892 * 512];

__device__ __forceinline__ float sigf(float x)     { return 1.f / (1.f + __expf(-x)); }
__device__ __forceinline__ float tanhfast(float x) { return 2.f / (1.f + __expf(-2.f * x)) - 1.f; }

__device__ __forceinline__ void ffma2(u64& d, u64 a, u64 b) {
    asm("fma.rn.f32x2 %0, %1, %2, %0;" : "+l"(d) : "l"(a), "l"(b));
}
__device__ __forceinline__ u64 pack2(float x) {
    u64 v; asm("mov.b64 %0, {%1, %1};" : "=l"(v) : "f"(x)); return v;
}
__device__ __forceinline__ float2 unpack2(u64 v) {
    float2 f; asm("mov.b64 {%0, %1}, %2;" : "=f"(f.x), "=f"(f.y) : "l"(v)); return f;
}

// ---- prologue: WT[k*512 + c] = W[c*KD + k] (coalesced writes) ----
__global__ void transpose_w(const float* __restrict__ W, float* __restrict__ WT, int KD)
{
    int i = blockIdx.x * blockDim.x + threadIdx.x;
    if (i < KD * 512) {
        int k = i >> 9, c = i & 511;
        WT[i] = W[c * KD + k];
    }
}

// stage one 16-k chunk of WT [KD x 512] (k-major) into smem: flat coalesced copy.
template <int KD>
__device__ __forceinline__ void stage_chunkT(const float* __restrict__ WT, int ci,
                                             float* __restrict__ Wt, int tid)
{
    const int k0   = 16 * ci;
    const int klen = (KD - k0 < 16) ? (KD - k0) : 16;
    const float4* src = (const float4*)(WT + (size_t)k0 * 512);
    float4* dst = (float4*)Wt;
    const int n4 = klen * 128;
#pragma unroll
    for (int l = 0; l < 8; ++l) {
        int i = tid + l * NT;
        if (i < n4) dst[i] = src[i];
    }
}

// compute one staged chunk: act rows r0..r0+7 (this thread), nk2 groups of 2 k.
// cb0 = 64*ch + 2*tx : this thread's column pair base within each gate.
__device__ __forceinline__ void gemm_chunk2(const float* __restrict__ act, int pitch,
                                            const float* __restrict__ Wt, int cb0,
                                            u64 (&acc)[8][4], int nk2)
{
    for (int q = 0; q < nk2; ++q) {
        float2 a[8];
#pragma unroll
        for (int r = 0; r < 8; ++r)
            a[r] = *(const float2*)(act + r * pitch + 2 * q);
#pragma unroll
        for (int kk = 0; kk < 2; ++kk) {
            const float* wb = Wt + (2 * q + kk) * 512 + cb0;
            u64 w0 = *(const u64*)(wb);
            u64 w1 = *(const u64*)(wb + 128);
            u64 w2 = *(const u64*)(wb + 256);
            u64 w3 = *(const u64*)(wb + 384);
#pragma unroll
            for (int r = 0; r < 8; ++r) {
                u64 p = pack2(kk ? a[r].y : a[r].x);
                ffma2(acc[r][0], p, w0);
                ffma2(acc[r][1], p, w1);
                ffma2(acc[r][2], p, w2);
                ffma2(acc[r][3], p, w3);
            }
        }
    }
}

// one full GEMM pass over transposed weights WT [KD x 512] against act.
template <int KD>
__device__ __forceinline__ void gemm_pass(const float* __restrict__ WT,
                                          const float* __restrict__ act, int pitch,
                                          float* __restrict__ Wt0, float* __restrict__ Wt1,
                                          int tid, int cb0, u64 (&acc)[8][4])
{
    constexpr int NCH = (KD + 15) >> 4;
    stage_chunkT<KD>(WT, 0, Wt0, tid);
    __syncthreads();
#pragma unroll
    for (int ci = 0; ci < NCH; ++ci) {
        float* cw = (ci & 1) ? Wt1 : Wt0;
        float* nw = (ci & 1) ? Wt0 : Wt1;
        if (ci + 1 < NCH) stage_chunkT<KD>(WT, ci + 1, nw, tid);
        const int klen = (KD - 16 * ci < 16) ? (KD - 16 * ci) : 16;
        gemm_chunk2(act + 16 * ci, pitch, cw, cb0, acc, klen >> 1);
        __syncthreads();
    }
}

template <int DIN, int MODE, int BCAST>
__global__ __launch_bounds__(NT, 2)
void lstm_kernel(const float* __restrict__ X,
                 const float* __restrict__ WihT, const float* __restrict__ WhhT,
                 const float* __restrict__ bih, const float* __restrict__ bhh,
                 const float* __restrict__ Waux, const float* __restrict__ baux,
                 float* __restrict__ OutSeq, float* __restrict__ OutAux)
{
    constexpr int XP = (DIN + 3) & ~3;       // padded act pitch (60/64/128)
    extern __shared__ float sm[];
    float* Hbuf   = sm;                       // 4096
    float* Xbuf   = sm + 4096;                // 32*XP
    float* bias_s = Xbuf + MR * XP;           // 512
    float* Wt0    = bias_s + 512;             // 8192
    float* Wt1    = Wt0 + 8192;               // 8192
    float* Waux_s = Wt0 + 16384;              // MODE2: 60*132 = 7920

    const int tid = threadIdx.x;
    const int tx  = tid & 31;
    const int ty  = tid >> 5;                 // 0..7
    const int r0  = (ty >> 1) * 8;            // row group base
    const int cb0 = (ty & 1) * 64 + 2 * tx;   // column pair base within a gate
    const int rowbase = blockIdx.x * MR;

    for (int i = tid; i < 512; i += NT) bias_s[i] = bih[i] + bhh[i];
    if (MODE == 2) {
        for (int i = tid; i < CD * CH; i += NT) {
            int c = i >> 7, k = i & 127;
            Waux_s[c * 132 + k] = Waux[i];
        }
    }
    if (BCAST) {
        constexpr int VPR = DIN / 4;
        for (int i = tid; i < MR * VPR; i += NT) {
            int r = i / VPR, v = i - r * VPR;
            *(float4*)(Xbuf + r * XP + 4 * v) =
                *((const float4*)(X + (size_t)(rowbase + r) * DIN) + v);
        }
    }

    float cst[8][2];
#pragma unroll
    for (int r = 0; r < 8; r++) { cst[r][0] = 0.f; cst[r][1] = 0.f; }
    u64 acc[8][4];
    __syncthreads(); // bias/Waux/Xbuf(bcast) visible

    for (int t = 0; t < CT; ++t) {
        if (!BCAST) {
            constexpr int VPR = DIN / 4; // 15 or 32
            for (int i = tid; i < MR * VPR; i += NT) {
                int r = i / VPR, v = i - r * VPR;
                *(float4*)(Xbuf + r * XP + 4 * v) =
                    *((const float4*)(X + ((size_t)(rowbase + r) * CT + t) * DIN) + v);
            }
        }
        // acc init from bias (one u64 per gate, replicated to 8 rows)
        {
            const float* bb = bias_s + cb0;
#pragma unroll
            for (int j = 0; j < 4; j++) {
                u64 b = *(const u64*)(bb + 128 * j);
#pragma unroll
                for (int r = 0; r < 8; r++) acc[r][j] = b;
            }
        }

        gemm_pass<DIN>(WihT, Xbuf + r0 * XP, XP, Wt0, Wt1, tid, cb0, acc);
        if (t > 0)
            gemm_pass<CH>(WhhT, Hbuf + r0 * CH, CH, Wt0, Wt1, tid, cb0, acc);
        __syncthreads(); // all reads of Hbuf/Xbuf for this timestep complete

        // ---- cell update; thread h-cols = cb0 + {0,1} ----
#pragma unroll
        for (int r = 0; r < 8; r++) {
            float2 iv = unpack2(acc[r][0]);
            float2 fv = unpack2(acc[r][1]);
            float2 gv = unpack2(acc[r][2]);
            float2 ov = unpack2(acc[r][3]);
            float h0, h1;
            {
                float ig = sigf(iv.x), fg = sigf(fv.x);
                float gg = tanhfast(gv.x), og = sigf(ov.x);
                float cv = fmaf(fg, cst[r][0], ig * gg);
                cst[r][0] = cv;
                h0 = og * tanhfast(cv);
            }
            {
                float ig = sigf(iv.y), fg = sigf(fv.y);
                float gg = tanhfast(gv.y), og = sigf(ov.y);
                float cv = fmaf(fg, cst[r][1], ig * gg);
                cst[r][1] = cv;
                h1 = og * tanhfast(cv);
            }
            float2 h2 = make_float2(h0, h1);
            *(float2*)(Hbuf + (r0 + r) * CH + cb0) = h2;
            if (MODE == 0) {
                *(float2*)(OutSeq + ((size_t)(rowbase + r0 + r) * CT + t) * CH + cb0) = h2;
            }
        }

        if (MODE == 2) {
            __syncthreads(); // h_t complete in Hbuf
            // out_t[32][60] = h_t @ W_out^T + b_out ; r warp-uniform -> broadcast h,
            // Waux pitch 132 -> conflict-free float4 per 8-lane phase.
#pragma unroll
            for (int l = 0; l < 8; l++) {
                int i = tid + l * NT;
                int r = i >> 6, c = i & 63;
                if (c < CD) {
                    const float4* h4 = (const float4*)(Hbuf + r * CH);
                    const float4* w4 = (const float4*)(Waux_s + c * 132);
                    float sum = __ldg(baux + c);
#pragma unroll 8
                    for (int k4 = 0; k4 < 32; k4++) {
                        float4 hh = h4[k4], ww = w4[k4];
                        sum = fmaf(hh.x, ww.x, sum); sum = fmaf(hh.y, ww.y, sum);
                        sum = fmaf(hh.z, ww.z, sum); sum = fmaf(hh.w, ww.w, sum);
                    }
                    OutAux[((size_t)(rowbase + r) * CT + t) * CD + c] = sum;
                }
            }
            // next t's first pass barrier orders any Wt/Hbuf re-writes after this.
        }
    }

    if (MODE == 1) {
        // z[32][64] = h_last @ W_lat^T + b_lat ; stage W_lat at pitch 132 in Wt region
        __syncthreads();
        for (int i = tid; i < CL * CH; i += NT) {
            int c = i >> 7, k = i & 127;
            Wt0[c * 132 + k] = Waux[i]; // 16384-float Wt region fits 64*132
        }
        __syncthreads();
#pragma unroll
        for (int l = 0; l < 8; l++) {
            int i = tid + l * NT;
            int r = i >> 6, c = i & 63;
            const float4* h4 = (const float4*)(Hbuf + r * CH);
            const float4* w4 = (const float4*)(Wt0 + c * 132);
            float sum = __ldg(baux + c);
#pragma unroll 8
            for (int k4 = 0; k4 < 32; k4++) {
                float4 hh = h4[k4], ww = w4[k4];
                sum = fmaf(hh.x, ww.x, sum); sum = fmaf(hh.y, ww.y, sum);
                sum = fmaf(hh.z, ww.z, sum); sum = fmaf(hh.w, ww.w, sum);
            }
            OutAux[(size_t)(rowbase + r) * CL + c] = sum;
        }
    }
}

// ----------------------------------------------------------------------------

extern "C" void kernel_launch(void* const* d_in, const int* in_sizes, int n_in,
                              void* d_out, int out_size)
{
    const float* x     = (const float*)d_in[0];
    const float* e0Wih = (const float*)d_in[1];
    const float* e0Whh = (const float*)d_in[2];
    const float* e0bih = (const float*)d_in[3];
    const float* e0bhh = (const float*)d_in[4];
    const float* e1Wih = (const float*)d_in[5];
    const float* e1Whh = (const float*)d_in[6];
    const float* e1bih = (const float*)d_in[7];
    const float* e1bhh = (const float*)d_in[8];
    const float* d0Wih = (const float*)d_in[9];
    const float* d0Whh = (const float*)d_in[10];
    const float* d0bih = (const float*)d_in[11];
    const float* d0bhh = (const float*)d_in[12];
    const float* d1Wih = (const float*)d_in[13];
    const float* d1Whh = (const float*)d_in[14];
    const float* d1bih = (const float*)d_in[15];
    const float* d1bhh = (const float*)d_in[16];
    const float* Wlat  = (const float*)d_in[17];
    const float* blat  = (const float*)d_in[18];
    const float* Wout  = (const float*)d_in[19];
    const float* bout  = (const float*)d_in[20];
    float* out = (float*)d_out;

    float *h1p, *d1p, *zp, *wtp;
    cudaGetSymbolAddress((void**)&h1p, g_h1);
    cudaGetSymbolAddress((void**)&d1p, g_d1);
    cudaGetSymbolAddress((void**)&zp,  g_z);
    cudaGetSymbolAddress((void**)&wtp, g_wt);

    // WT region offsets (rows of 512)
    const int R_E0IH = 0;            // KD=60
    const int R_E0HH = 60;           // KD=128
    const int R_E1IH = 188;          // KD=128
    const int R_E1HH = 316;          // KD=128
    const int R_D0IH = 444;          // KD=64
    const int R_D0HH = 508;          // KD=128
    const int R_D1IH = 636;          // KD=128
    const int R_D1HH = 764;          // KD=128  (end 892)

    struct { const float* src; int off; int kd; } tw[8] = {
        { e0Wih, R_E0IH, 60  }, { e0Whh, R_E0HH, 128 },
        { e1Wih, R_E1IH, 128 }, { e1Whh, R_E1HH, 128 },
        { d0Wih, R_D0IH, 64  }, { d0Whh, R_D0HH, 128 },
        { d1Wih, R_D1IH, 128 }, { d1Whh, R_D1HH, 128 },
    };
    for (int m = 0; m < 8; ++m) {
        int n = tw[m].kd * 512;
        transpose_w<<<(n + 255) / 256, 256>>>(tw[m].src, wtp + (size_t)tw[m].off * 512,
                                              tw[m].kd);
    }

    // smem (floats): Hbuf 4096 + Xbuf 32*XP + bias 512 + Wt 16384 (+ MODE2 7920)
    const int SM_ENC0 = (4096 + 32 * 60  + 512 + 16384) * 4;          // 91,648
    const int SM_ENC1 = (4096 + 32 * 128 + 512 + 16384) * 4;          // 100,352
    const int SM_DEC0 = (4096 + 32 * 64  + 512 + 16384) * 4;          // 92,160
    const int SM_DEC1 = (4096 + 32 * 128 + 512 + 16384 + 7920) * 4;   // 132,032

    cudaFuncSetAttribute((const void*)lstm_kernel<60, 0, 0>,
                         cudaFuncAttributeMaxDynamicSharedMemorySize, SM_ENC0);
    cudaFuncSetAttribute((const void*)lstm_kernel<128, 1, 0>,
                         cudaFuncAttributeMaxDynamicSharedMemorySize, SM_ENC1);
    cudaFuncSetAttribute((const void*)lstm_kernel<64, 0, 1>,
                         cudaFuncAttributeMaxDynamicSharedMemorySize, SM_DEC0);
    cudaFuncSetAttribute((const void*)lstm_kernel<128, 2, 0>,
                         cudaFuncAttributeMaxDynamicSharedMemorySize, SM_DEC1);

    dim3 grid(CB / MR); // 2048 CTAs

    // encoder layer 0: x [B,T,60] -> h1 seq [B,T,128]
    lstm_kernel<60, 0, 0><<<grid, NT, SM_ENC0>>>(
        x, wtp + (size_t)R_E0IH * 512, wtp + (size_t)R_E0HH * 512,
        e0bih, e0bhh, nullptr, nullptr, h1p, nullptr);
    // encoder layer 1: h1 -> h_last -> z [B,64]
    lstm_kernel<128, 1, 0><<<grid, NT, SM_ENC1>>>(
        h1p, wtp + (size_t)R_E1IH * 512, wtp + (size_t)R_E1HH * 512,
        e1bih, e1bhh, Wlat, blat, nullptr, zp);
    // decoder layer 0: z broadcast over T -> d1 seq [B,T,128]
    lstm_kernel<64, 0, 1><<<grid, NT, SM_DEC0>>>(
        zp, wtp + (size_t)R_D0IH * 512, wtp + (size_t)R_D0HH * 512,
        d0bih, d0bhh, nullptr, nullptr, d1p, nullptr);
    // decoder layer 1 + output projection: d1 -> recon [B,T,60]
    lstm_kernel<128, 2, 0><<<grid, NT, SM_DEC1>>>(
        d1p, wtp + (size_t)R_D1IH * 512, wtp + (size_t)R_D1HH * 512,
        d1bih, d1bhh, Wout, bout, nullptr, out);
}

// round 17
// speedup vs baseline: 2.6249x; 2.6232x over previous
#include <cuda_runtime.h>
#include <cuda_bf16.h>

typedef unsigned long long u64;
typedef unsigned int u32;

#define CB 65536
#define CT 8
#define CD 60
#define CH 128
#define CL 64
#define MR 32
#define NT 256
#define NBLK (CB / MR)

// global scratch
__device__ __nv_bfloat16 g_h1[2ull * CB * CT * CH]; // enc0 h planes hi/lo (256MB)
__device__ __nv_bfloat16 g_d1[2ull * CB * CT * CH]; // dec0 h planes hi/lo (256MB)
__device__ float g_z[(size_t)CB * CL];              // latent (16MB)
__device__ uint4 g_wf[114688];                      // fragment-packed weights (1.75MB)

__device__ __forceinline__ float sigf(float x)     { return 1.f / (1.f + __expf(-x)); }
__device__ __forceinline__ float tanhfast(float x) { return 2.f / (1.f + __expf(-2.f * x)) - 1.f; }
__device__ __forceinline__ u32 p2(float a, float b) {
    __nv_bfloat162 t = __floats2bfloat162_rn(a, b);
    return *reinterpret_cast<u32*>(&t);
}
__device__ __forceinline__ float lopart(float a) {
    return a - __bfloat162float(__float2bfloat16(a));
}
__device__ __forceinline__ u32 smem_u32(const void* p) {
    u32 a; asm("{ .reg .u64 t; cvta.to.shared.u64 t, %1; cvt.u32.u64 %0, t; }" : "=r"(a) : "l"(p));
    return a;
}
__device__ __forceinline__ void mma16816(float* c, const u32* a, u32 b0, u32 b1) {
    asm volatile("mma.sync.aligned.m16n8k16.row.col.f32.bf16.bf16.f32 "
                 "{%0,%1,%2,%3}, {%4,%5,%6,%7}, {%8,%9}, {%0,%1,%2,%3};"
                 : "+f"(c[0]), "+f"(c[1]), "+f"(c[2]), "+f"(c[3])
                 : "r"(a[0]), "r"(a[1]), "r"(a[2]), "r"(a[3]), "r"(b0), "r"(b1));
}
__device__ __forceinline__ void ldsm4(u32* r, u32 addr) {
    asm volatile("ldmatrix.sync.aligned.m8n8.x4.shared.b16 {%0,%1,%2,%3}, [%4];"
                 : "=r"(r[0]), "=r"(r[1]), "=r"(r[2]), "=r"(r[3]) : "r"(addr));
}

// ---- prologue: pack W[512 x KD] into fragment-linear uint4s ----
// index i = ((s*4+g)*16 + nt)*32 + lane ; uint4 = {b0hi,b1hi,b0lo,b1lo}
// b0 = W[row][k0..k0+1], b1 = W[row][k0+8..k0+9]; row = 128g+8nt+(lane>>2),
// k0 = 16s + 2*(lane&3). Out-of-range k (KD=60 pad) -> 0.
__global__ void build_frag(const float* __restrict__ W, uint4* __restrict__ WF,
                           int KD, int S)
{
    int i = blockIdx.x * blockDim.x + threadIdx.x;
    if (i >= S * 2048) return;
    int lane = i & 31, nt = (i >> 5) & 15, g = (i >> 9) & 3, s = i >> 11;
    int row = 128 * g + 8 * nt + (lane >> 2);
    int k0 = 16 * s + 2 * (lane & 3);
    float v[4];
#pragma unroll
    for (int e = 0; e < 4; ++e) {
        int k = k0 + (e >> 1) * 8 + (e & 1);
        v[e] = (k < KD) ? W[(size_t)row * KD + k] : 0.f;
    }
    uint4 o;
    o.x = p2(v[0], v[1]);
    o.y = p2(v[2], v[3]);
    o.z = p2(lopart(v[0]), lopart(v[1]));
    o.w = p2(lopart(v[2]), lopart(v[3]));
    WF[i] = o;
}

// ---- one GEMM pass over nslab k-slabs; A from image pair (hi, hi+8704) ----
__device__ __forceinline__ void gemm(const uint4* __restrict__ WF, int nslab,
                                     u32 imgHi, int lm_off, int wn, int lane,
                                     float acc[4][4][4])
{
    for (int s = 0; s < nslab; ++s) {
        u32 ah[4], al[4];
        ldsm4(ah, imgHi + lm_off + 32 * s);
        ldsm4(al, imgHi + 8704 + lm_off + 32 * s);
        const uint4* base = WF + (size_t)s * 2048 + wn * 128 + lane;
#pragma unroll
        for (int g = 0; g < 4; ++g) {
#pragma unroll
            for (int j = 0; j < 4; ++j) {
                uint4 b = base[g * 512 + j * 32];
                mma16816(acc[g][j], ah, b.x, b.y);
                mma16816(acc[g][j], ah, b.z, b.w);
                mma16816(acc[g][j], al, b.x, b.y);
            }
        }
    }
}

// ----------------------------------------------------------------------------
// XSLAB: input k-slabs (4 or 8). MODE 0: h planes out; 1: z out; 2: recon out.
// XSRC 0: x from fp32 global (convert+split); 1: from bf16 hi/lo planes.
// BCAST: x constant over t (dec0).
// ----------------------------------------------------------------------------
template <int XSLAB, int MODE, int XSRC, int XD, int BCAST>
__global__ __launch_bounds__(NT, 2)
void lstm_mma(const void* __restrict__ Xin,
              const uint4* __restrict__ WFih, const uint4* __restrict__ WFhh,
              const float* __restrict__ bih, const float* __restrict__ bhh,
              const float* __restrict__ Waux, const float* __restrict__ baux,
              __nv_bfloat16* __restrict__ OutImg, float* __restrict__ OutAux)
{
    constexpr int WAUXN = (MODE == 1) ? CL : (MODE == 2 ? CD : 0);
    constexpr int WAUXB = WAUXN * 132 * 4;
    constexpr int O_XHI = 2048 + WAUXB;           // x images: hi, lo (8704 each)
    constexpr int O_HHI = O_XHI + 17408;          // h images: hi, lo
    constexpr int O_HF  = O_HHI + 17408;          // fp32 h stash (MODE1/2)

    extern __shared__ char smc[];
    const u32 sb = smem_u32(smc);
    float* bias_s = (float*)smc;
    float* waux_s = (float*)(smc + 2048);
    float* Hf     = (float*)(smc + O_HF);

    const int tid = threadIdx.x, lane = tid & 31, wid = tid >> 5;
    const int wn = wid & 3, wm = wid >> 2;
    const int blk = blockIdx.x, rowbase = blk * MR;

    for (int i = tid; i < 512; i += NT) bias_s[i] = bih[i] + bhh[i];
    if (MODE)
        for (int i = tid; i < WAUXN * CH; i += NT) {
            int c = i >> 7, k = i & 127;
            waux_s[c * 132 + k] = Waux[i];
        }

    // ldmatrix per-lane address offset within an image
    const int quad = lane >> 3;
    const int lm_off = (16 * wm + (quad & 1) * 8 + (lane & 7)) * 272 + (quad >> 1) * 16;
    // epilogue coords
    const int R0 = 16 * wm + (lane >> 2);

    float cst[4][4];
#pragma unroll
    for (int j = 0; j < 4; ++j)
#pragma unroll
        for (int e = 0; e < 4; ++e) cst[j][e] = 0.f;

    for (int t = 0; t < CT; ++t) {
        // ---- stage x images ----
        if (XSRC == 0) {
            if (!BCAST || t == 0) {
                for (int i = tid; i < 32 * 16; i += NT) {
                    int r = i >> 4, v = i & 15;
                    u64 hw = 0, lw = 0;
                    if (!(XD == 60 && v == 15)) {
                        const float* rp = BCAST
                            ? (const float*)Xin + (size_t)(rowbase + r) * XD
                            : (const float*)Xin + ((size_t)(rowbase + r) * CT + t) * XD;
                        float4 x4 = ((const float4*)rp)[v];
                        hw = (u64)p2(x4.x, x4.y) | ((u64)p2(x4.z, x4.w) << 32);
                        lw = (u64)p2(lopart(x4.x), lopart(x4.y))
                           | ((u64)p2(lopart(x4.z), lopart(x4.w)) << 32);
                    }
                    *(u64*)(smc + O_XHI + r * 272 + 8 * v) = hw;
                    *(u64*)(smc + O_XHI + 8704 + r * 272 + 8 * v) = lw;
                }
            }
        } else {
            const size_t PL = (size_t)CB * CT * CH;
            for (int i = tid; i < 1024; i += NT) {
                int p = i >> 9, idx = i & 511, r = idx >> 4, v = idx & 15;
                const uint4* src = (const uint4*)((const __nv_bfloat16*)Xin + p * PL)
                                   + ((size_t)(rowbase + r) * CT + t) * 16 + v;
                *(uint4*)(smc + O_XHI + p * 8704 + r * 272 + 16 * v) = *src;
            }
        }
        __syncthreads(); // Xs staged; prior-t Hs writes visible

        float acc[4][4][4];
#pragma unroll
        for (int g = 0; g < 4; ++g)
#pragma unroll
            for (int j = 0; j < 4; ++j)
#pragma unroll
                for (int e = 0; e < 4; ++e) acc[g][j][e] = 0.f;

        gemm(WFih, XSLAB, sb + O_XHI, lm_off, wn, lane, acc);
        if (t > 0) gemm(WFhh, 8, sb + O_HHI, lm_off, wn, lane, acc);
        __syncthreads(); // all image reads done before Hs overwrite

        // ---- cell update (acc-fragment layout) + h image writes ----
#pragma unroll
        for (int j = 0; j < 4; ++j) {
            const int cp = 32 * wn + 8 * j + 2 * (lane & 3);
            float hv[4];
#pragma unroll
            for (int e = 0; e < 4; ++e) {
                const int bo = cp + (e & 1);
                float gi = sigf(acc[0][j][e] + bias_s[bo]);
                float gf = sigf(acc[1][j][e] + bias_s[128 + bo]);
                float gg = tanhfast(acc[2][j][e] + bias_s[256 + bo]);
                float go = sigf(acc[3][j][e] + bias_s[384 + bo]);
                float cv = fmaf(gf, cst[j][e], gi * gg);
                cst[j][e] = cv;
                hv[e] = go * tanhfast(cv);
            }
            *(u32*)(smc + O_HHI + R0 * 272 + 2 * cp)        = p2(hv[0], hv[1]);
            *(u32*)(smc + O_HHI + (R0 + 8) * 272 + 2 * cp)  = p2(hv[2], hv[3]);
            *(u32*)(smc + O_HHI + 8704 + R0 * 272 + 2 * cp) =
                p2(lopart(hv[0]), lopart(hv[1]));
            *(u32*)(smc + O_HHI + 8704 + (R0 + 8) * 272 + 2 * cp) =
                p2(lopart(hv[2]), lopart(hv[3]));
            if (MODE == 2 || (MODE == 1 && t == CT - 1)) {
                Hf[R0 * 132 + cp] = hv[0];
                Hf[R0 * 132 + cp + 1] = hv[1];
                Hf[(R0 + 8) * 132 + cp] = hv[2];
                Hf[(R0 + 8) * 132 + cp + 1] = hv[3];
            }
        }
        __syncthreads(); // Hs / Hf visible

        if (MODE == 0) { // h images -> global planes (coalesced uint4)
            const size_t PL = (size_t)CB * CT * CH;
            for (int i = tid; i < 1024; i += NT) {
                int p = i >> 9, idx = i & 511, r = idx >> 4, v = idx & 15;
                uint4* dst = (uint4*)(OutImg + p * PL)
                             + ((size_t)(rowbase + r) * CT + t) * 16 + v;
                *dst = *(const uint4*)(smc + O_HHI + p * 8704 + r * 272 + 16 * v);
            }
        }
        if (MODE == 2) { // out_t[32,60] = h_t @ W_out^T + b_out
#pragma unroll
            for (int l = 0; l < 8; ++l) {
                int i = tid + l * NT;
                int r = i >> 6, c = i & 63;
                if (c < CD) {
                    const float4* h4 = (const float4*)(Hf + r * 132);
                    const float4* w4 = (const float4*)(waux_s + c * 132);
                    float sum = __ldg(baux + c);
#pragma unroll 8
                    for (int k4 = 0; k4 < 32; k4++) {
                        float4 hh = h4[k4], ww = w4[k4];
                        sum = fmaf(hh.x, ww.x, sum); sum = fmaf(hh.y, ww.y, sum);
                        sum = fmaf(hh.z, ww.z, sum); sum = fmaf(hh.w, ww.w, sum);
                    }
                    OutAux[((size_t)(rowbase + r) * CT + t) * CD + c] = sum;
                }
            }
        }
    }

    if (MODE == 1) { // z[32,64] = h_last @ W_lat^T + b_lat
#pragma unroll
        for (int l = 0; l < 8; ++l) {
            int i = tid + l * NT;
            int r = i >> 6, c = i & 63;
            const float4* h4 = (const float4*)(Hf + r * 132);
            const float4* w4 = (const float4*)(waux_s + c * 132);
            float sum = __ldg(baux + c);
#pragma unroll 8
            for (int k4 = 0; k4 < 32; k4++) {
                float4 hh = h4[k4], ww = w4[k4];
                sum = fmaf(hh.x, ww.x, sum); sum = fmaf(hh.y, ww.y, sum);
                sum = fmaf(hh.z, ww.z, sum); sum = fmaf(hh.w, ww.w, sum);
            }
            OutAux[(size_t)(rowbase + r) * CL + c] = sum;
        }
    }
}

// ----------------------------------------------------------------------------

extern "C" void kernel_launch(void* const* d_in, const int* in_sizes, int n_in,
                              void* d_out, int out_size)
{
    const float* x = (const float*)d_in[0];
    const float* W8[8] = { (const float*)d_in[1],  (const float*)d_in[2],
                           (const float*)d_in[5],  (const float*)d_in[6],
                           (const float*)d_in[9],  (const float*)d_in[10],
                           (const float*)d_in[13], (const float*)d_in[14] };
    const float* e0bih = (const float*)d_in[3],  *e0bhh = (const float*)d_in[4];
    const float* e1bih = (const float*)d_in[7],  *e1bhh = (const float*)d_in[8];
    const float* d0bih = (const float*)d_in[11], *d0bhh = (const float*)d_in[12];
    const float* d1bih = (const float*)d_in[15], *d1bhh = (const float*)d_in[16];
    const float* Wlat = (const float*)d_in[17], *blat = (const float*)d_in[18];
    const float* Wout = (const float*)d_in[19], *bout = (const float*)d_in[20];
    float* out = (float*)d_out;

    __nv_bfloat16 *h1p, *d1p; float* zp; uint4* wfp;
    cudaGetSymbolAddress((void**)&h1p, g_h1);
    cudaGetSymbolAddress((void**)&d1p, g_d1);
    cudaGetSymbolAddress((void**)&zp,  g_z);
    cudaGetSymbolAddress((void**)&wfp, g_wf);

    // fragment regions (uint4 units); ih first, hh second per layer
    const int off[8] = { 0, 8192, 24576, 40960, 57344, 65536, 81920, 98304 };
    const int kd [8] = { 60, 128, 128, 128, 64, 128, 128, 128 };
    for (int m = 0; m < 8; ++m) {
        int S = (kd[m] > 64) ? 8 : 4;
        int n = S * 2048;
        build_frag<<<(n + 255) / 256, 256>>>(W8[m], wfp + off[m], kd[m], S);
    }

    const int SM_M0 = 2048 + 34816;                       // 36,864
    const int SM_M1 = 2048 + 64 * 132 * 4 + 34816 + 16896; // 87,552
    const int SM_M2 = 2048 + 60 * 132 * 4 + 34816 + 16896; // 85,440

    cudaFuncSetAttribute((const void*)lstm_mma<4, 0, 0, 60, 0>,
                         cudaFuncAttributeMaxDynamicSharedMemorySize, SM_M0);
    cudaFuncSetAttribute((const void*)lstm_mma<8, 1, 1, 128, 0>,
                         cudaFuncAttributeMaxDynamicSharedMemorySize, SM_M1);
    cudaFuncSetAttribute((const void*)lstm_mma<4, 0, 0, 64, 1>,
                         cudaFuncAttributeMaxDynamicSharedMemorySize, SM_M0);
    cudaFuncSetAttribute((const void*)lstm_mma<8, 2, 1, 128, 0>,
                         cudaFuncAttributeMaxDynamicSharedMemorySize, SM_M2);

    // enc0: x fp32 -> h1 planes
    lstm_mma<4, 0, 0, 60, 0><<<NBLK, NT, SM_M0>>>(
        x, wfp + off[0], wfp + off[1], e0bih, e0bhh, nullptr, nullptr, h1p, nullptr);
    // enc1: h1 planes -> z
    lstm_mma<8, 1, 1, 128, 0><<<NBLK, NT, SM_M1>>>(
        h1p, wfp + off[2], wfp + off[3], e1bih, e1bhh, Wlat, blat, nullptr, zp);
    // dec0: z (bcast) -> d1 planes
    lstm_mma<4, 0, 0, 64, 1><<<NBLK, NT, SM_M0>>>(
        zp, wfp + off[4], wfp + off[5], d0bih, d0bhh, nullptr, nullptr, d1p, nullptr);
    // dec1: d1 planes -> recon
    lstm_mma<8, 2, 1, 128, 0><<<NBLK, NT, SM_M2>>>(
        d1p, wfp + off[6], wfp + off[7], d1bih, d1bhh, Wout, bout, nullptr, out);
}